// round 16
// baseline (speedup 1.0000x reference)
#include <cuda_runtime.h>
#include <math.h>
#include <stdint.h>

// ---------------- problem constants ----------------
#define S     64
#define SS    (S*S)
#define SSS   (S*S*S)
#define C_IN  16
#define C_HID 64
#define NELEM (C_IN*SSS)       // 4194304
#define NSTEPS 20
#define DT_F   0.05f
#define SN_F   (0.1f * 0.22360679774997896f)

#define PD    66               // padded side (zero shell)
#define PCH   (PD*PD*PD)       // 287496 voxels padded
#define HCH   (PCH*8)          // floats per 8-channel h chunk

// common row layout: one (z,y) row = [plane0: 66 vox x 4ch x 4B][plane1]
#define ROWB  2112
#define PLOFF 1056             // plane1 byte offset within row

// conv1 tile: x:64, y:2, z:1 (M=128), 8 warps; 2 ic-chunks of 8, pipelined
#define T1NR  12               // 3 z x 4 y rows
#define T1CH  (T1NR*ROWB)      // 25344 B per chunk buffer
// conv2 tile: x:64, y:4, z:2 (M=512), 8 warps, M=64/warp; 8 ic-chunks of 8
#define T2NR  24               // 4 z x 6 y rows
#define T2CH  (T2NR*ROWB)      // 50688 B per chunk buffer

// ---------------- device scratch (allocation-free; zero-init shells) -------
__device__ float g_ypad[PCH*16];        // y fp32 state, padded CL [z][y][x][16]
__device__ float g_ytf32[PCH*16];       // tf32-rounded shadow (conv1 input)
__device__ float g_h[HCH*8];            // h, 8 chunks of [z][y][x][8] (tf32 bits)
__device__ float g_wf1[27*2*8*32*2];    // conv1 B-frags [tap][ks][nt][lane][2]
__device__ float g_wf2[8*27*2*32*2];    // conv2 B-frags [ch][tap][nt][lane][2]

// ---------------- PTX helpers ----------------
__device__ __forceinline__ uint32_t cvt_tf32(float f) {
    uint32_t r;
    asm("cvt.rna.tf32.f32 %0, %1;" : "=r"(r) : "f"(f));
    return r;
}
__device__ __forceinline__ uint32_t lds_u(uint32_t a) {
    uint32_t v;
    asm volatile("ld.shared.b32 %0, [%1];" : "=r"(v) : "r"(a));
    return v;
}
__device__ __forceinline__ void mma_tf32(float* d, uint32_t a0, uint32_t a1,
                                         uint32_t a2, uint32_t a3,
                                         uint32_t b0, uint32_t b1) {
    asm volatile(
        "mma.sync.aligned.m16n8k8.row.col.f32.tf32.tf32.f32 "
        "{%0,%1,%2,%3}, {%4,%5,%6,%7}, {%8,%9}, {%0,%1,%2,%3};"
        : "+f"(d[0]), "+f"(d[1]), "+f"(d[2]), "+f"(d[3])
        : "r"(a0), "r"(a1), "r"(a2), "r"(a3), "r"(b0), "r"(b1));
}
__device__ __forceinline__ void cp16(uint32_t dst, const void* src) {
    asm volatile("cp.async.cg.shared.global [%0], [%1], 16;"
                 :: "r"(dst), "l"(src));
}
__device__ __forceinline__ void cp_commit() {
    asm volatile("cp.async.commit_group;");
}
template<int N> __device__ __forceinline__ void cp_wait() {
    asm volatile("cp.async.wait_group %0;" :: "n"(N));
}

// ---------------------------------------------------------------------------
// Weight reorder into mma B-fragment layout (tf32-rounded).
// ---------------------------------------------------------------------------
__global__ void reorder_k(const float* __restrict__ w1,
                          const float* __restrict__ w2) {
    int i = blockIdx.x * blockDim.x + threadIdx.x;
    if (i >= 27648) return;
    {   // conv1: w1[oc64][ic16][27]
        int j = i & 1, lane = (i >> 1) & 31, nt = (i >> 6) & 7,
            ks = (i >> 9) & 1, tap = i >> 10;
        int oc = nt * 8 + (lane >> 2);
        int ic = ks * 8 + (lane & 3) + j * 4;
        g_wf1[i] = __uint_as_float(cvt_tf32(w1[(oc * 16 + ic) * 27 + tap]));
    }
    {   // conv2: w2[oc16][ic64][27]
        int j = i & 1, lane = (i >> 1) & 31, nt = (i >> 6) & 1;
        int t2 = i >> 7, tap = t2 % 27, ch = t2 / 27;
        int oc = nt * 8 + (lane >> 2);
        int ic = ch * 8 + (lane & 3) + j * 4;
        g_wf2[i] = __uint_as_float(cvt_tf32(w2[(oc * 64 + ic) * 27 + tap]));
    }
}

// ---------------------------------------------------------------------------
// Pack / unpack
// ---------------------------------------------------------------------------
__global__ void pack_k(const float* __restrict__ xin) {
    int e = blockIdx.x * blockDim.x + threadIdx.x;
    if (e >= NELEM) return;
    int c = e & 15, v = e >> 4;
    int x = v & 63, y = (v >> 6) & 63, z = v >> 12;
    float val = xin[c * SSS + v];
    int pi = ((((z + 1) * PD) + y + 1) * PD + x + 1) * 16 + c;
    g_ypad[pi]  = val;
    g_ytf32[pi] = __uint_as_float(cvt_tf32(val));
}
__global__ void unpack_k(float* __restrict__ out) {
    int e = blockIdx.x * blockDim.x + threadIdx.x;
    if (e >= NELEM) return;
    int c = e & 15, v = e >> 4;
    int x = v & 63, y = (v >> 6) & 63, z = v >> 12;
    out[c * SSS + v] = g_ypad[((((z + 1) * PD) + y + 1) * PD + x + 1) * 16 + c];
}

// ---------------------------------------------------------------------------
// Conv1 (16 -> 64) + bias + tanh -> g_h.  Pipelined 2 chunks of 8 ic,
// plane-split rows (conflict-free 16B/voxel A loads), B-frags batched.
// ---------------------------------------------------------------------------
__device__ __forceinline__ void load_chunk1(uint32_t buf, int ch,
                                            int y0, int z0, int tid) {
    const float* base = g_ytf32 + ch * 8;
    for (int i = tid; i < T1NR * 66; i += 256) {
        int row = i / 66, xp = i % 66;
        int zi = row >> 2, yi = row & 3;
        const float* src = base + ((((z0 + zi) * PD) + y0 + yi) * PD + xp) * 16;
        uint32_t dst = buf + (uint32_t)(row * ROWB + xp * 16);
        cp16(dst,         src);       // ic 0-3 of chunk -> plane 0
        cp16(dst + PLOFF, src + 4);   // ic 4-7 of chunk -> plane 1
    }
}

__global__ __launch_bounds__(256, 2)
void conv1_k(const float* __restrict__ b1) {
    extern __shared__ float sm[];
    const int tid = threadIdx.x, lane = tid & 31, w = tid >> 5;
    const int x0w = (w & 3) * 16, yw = w >> 2;
    const int y0 = blockIdx.x * 2, z0 = blockIdx.y;

    const uint32_t tb = (uint32_t)__cvta_generic_to_shared(sm);

    float d[8][4];
    const int c0 = (lane & 3) * 2;
    #pragma unroll
    for (int nt = 0; nt < 8; nt++) {
        float bl = __ldg(b1 + nt * 8 + c0), bh = __ldg(b1 + nt * 8 + c0 + 1);
        d[nt][0] = bl; d[nt][1] = bh; d[nt][2] = bl; d[nt][3] = bh;
    }

    const uint32_t loff = (uint32_t)((lane >> 2) * 16 + (lane & 3) * 4);

    load_chunk1(tb, 0, y0, z0, tid);
    cp_commit();
    load_chunk1(tb + T1CH, 1, y0, z0, tid);
    cp_commit();

    #pragma unroll 1
    for (int ch = 0; ch < 2; ch++) {
        if (ch == 0) cp_wait<1>(); else cp_wait<0>();
        __syncthreads();

        const uint32_t cb = tb + (uint32_t)(ch * T1CH);

        #pragma unroll 1
        for (int dz = 0; dz < 3; dz++) {
            #pragma unroll 1
            for (int dy = 0; dy < 3; dy++) {
                const uint32_t rbase =
                    cb + (uint32_t)((dz * 4 + yw + dy) * ROWB) + loff;
                const int tap = (dz * 3 + dy) * 3;
                #pragma unroll
                for (int dx = 0; dx < 3; dx++) {
                    const uint32_t ab = rbase + (uint32_t)((x0w + dx) * 16);
                    const float* wk = g_wf1 + (tap + dx) * 1024 + ch * 512
                                      + lane * 2;
                    uint2 bb[8];
                    #pragma unroll
                    for (int nt = 0; nt < 8; nt++)
                        bb[nt] = __ldg((const uint2*)(wk + nt * 64));
                    uint32_t a0 = lds_u(ab);
                    uint32_t a1 = lds_u(ab + 128);
                    uint32_t a2 = lds_u(ab + PLOFF);
                    uint32_t a3 = lds_u(ab + PLOFF + 128);
                    #pragma unroll
                    for (int nt = 0; nt < 8; nt++)
                        mma_tf32(d[nt], a0, a1, a2, a3, bb[nt].x, bb[nt].y);
                }
            }
        }
        if (ch == 0) __syncthreads();   // done reading buf0? no-op safety:
        // (buf0 and buf1 are distinct; barrier only orders chunk transition)
    }

    // epilogue: tanh + tf32-round, store to h chunks
    const int zp = z0 + 1, yp = y0 + yw + 1;
    const int hrow = ((zp * PD + yp) * PD + 1 + x0w) * 8 + (lane >> 2) * 8 + c0;
    #pragma unroll
    for (int nt = 0; nt < 8; nt++) {
        int a0i = nt * HCH + hrow;
        float2 lo, hi;
        lo.x = __uint_as_float(cvt_tf32(tanhf(d[nt][0])));
        lo.y = __uint_as_float(cvt_tf32(tanhf(d[nt][1])));
        hi.x = __uint_as_float(cvt_tf32(tanhf(d[nt][2])));
        hi.y = __uint_as_float(cvt_tf32(tanhf(d[nt][3])));
        *(float2*)&g_h[a0i]      = lo;
        *(float2*)&g_h[a0i + 64] = hi;
    }
}

// ---------------------------------------------------------------------------
// Conv2 (64 -> 16) + fused Euler update.  y:4,z:2 tile, M=64/warp,
// 8 chains; B-frags for all 3 dx hoisted per (dz,dy).
// ---------------------------------------------------------------------------
__device__ __forceinline__ void load_chunk2(uint32_t buf, int ch,
                                            int y0, int z0, int tid) {
    const float* base = g_h + ch * HCH;
    for (int i = tid; i < T2NR * 66; i += 256) {
        int row = i / 66, xp = i % 66;
        int zi = row / 6, yi = row % 6;
        const float* src = base + ((((z0 + zi) * PD) + y0 + yi) * PD + xp) * 8;
        uint32_t dst = buf + (uint32_t)(row * ROWB + xp * 16);
        cp16(dst,         src);
        cp16(dst + PLOFF, src + 4);
    }
}

__global__ __launch_bounds__(256, 2)
void conv2_k(const float* __restrict__ b2, const float* __restrict__ nz) {
    extern __shared__ float sm[];
    const int tid = threadIdx.x, lane = tid & 31, w = tid >> 5;
    const int yw = w & 3, zw = w >> 2;
    const int y0 = blockIdx.x * 4, z0 = blockIdx.y * 2;

    const uint32_t tb = (uint32_t)__cvta_generic_to_shared(sm);

    float d[4][2][4];
    #pragma unroll
    for (int mt = 0; mt < 4; mt++)
        #pragma unroll
        for (int nt = 0; nt < 2; nt++)
            d[mt][nt][0] = d[mt][nt][1] = d[mt][nt][2] = d[mt][nt][3] = 0.f;

    const uint32_t loff = (uint32_t)((lane >> 2) * 16 + (lane & 3) * 4);

    load_chunk2(tb, 0, y0, z0, tid);
    cp_commit();

    #pragma unroll 1
    for (int ch = 0; ch < 8; ch++) {
        __syncthreads();
        if (ch + 1 < 8) {
            load_chunk2(tb + (uint32_t)(((ch + 1) & 1) * T2CH),
                        ch + 1, y0, z0, tid);
            cp_commit();
            cp_wait<1>();
        } else {
            cp_wait<0>();
        }
        __syncthreads();

        const uint32_t cb = tb + (uint32_t)((ch & 1) * T2CH);
        const float* wch = g_wf2 + ch * 3456 + lane * 2;

        #pragma unroll 1
        for (int dz = 0; dz < 3; dz++) {
            #pragma unroll 1
            for (int dy = 0; dy < 3; dy++) {
                const uint32_t rbase =
                    cb + (uint32_t)(((zw + dz) * 6 + yw + dy) * ROWB) + loff;
                const int tap = (dz * 3 + dy) * 3;
                // hoist all 6 B-frags for this row (3 dx x 2 nt)
                const float* wt = wch + tap * 128;
                uint2 b00 = __ldg((const uint2*)(wt));
                uint2 b01 = __ldg((const uint2*)(wt + 64));
                uint2 b10 = __ldg((const uint2*)(wt + 128));
                uint2 b11 = __ldg((const uint2*)(wt + 192));
                uint2 b20 = __ldg((const uint2*)(wt + 256));
                uint2 b21 = __ldg((const uint2*)(wt + 320));
                #pragma unroll
                for (int dx = 0; dx < 3; dx++) {
                    uint2 bn0 = dx == 0 ? b00 : (dx == 1 ? b10 : b20);
                    uint2 bn1 = dx == 0 ? b01 : (dx == 1 ? b11 : b21);
                    #pragma unroll
                    for (int mt = 0; mt < 4; mt++) {
                        const uint32_t ab =
                            rbase + (uint32_t)((mt * 16 + dx) * 16);
                        uint32_t a0 = lds_u(ab);
                        uint32_t a1 = lds_u(ab + 128);
                        uint32_t a2 = lds_u(ab + PLOFF);
                        uint32_t a3 = lds_u(ab + PLOFF + 128);
                        mma_tf32(d[mt][0], a0, a1, a2, a3, bn0.x, bn0.y);
                        mma_tf32(d[mt][1], a0, a1, a2, a3, bn1.x, bn1.y);
                    }
                }
            }
        }
    }

    // fused Euler update: y += (f + b2)*dt + sn*z; fp32 + tf32 shadow
    const int c0 = (lane & 3) * 2;
    const int r  = lane >> 2;
    const int gy = y0 + yw, gz = z0 + zw;
    float bl[2], bh[2];
    #pragma unroll
    for (int nt = 0; nt < 2; nt++) {
        bl[nt] = __ldg(b2 + nt * 8 + c0);
        bh[nt] = __ldg(b2 + nt * 8 + c0 + 1);
    }
    #pragma unroll
    for (int mt = 0; mt < 4; mt++) {
        #pragma unroll
        for (int nt = 0; nt < 2; nt++) {
            int cc = nt * 8 + c0;
            #pragma unroll
            for (int half = 0; half < 2; half++) {
                int v  = mt * 16 + r + half * 8;
                int yi = (((gz + 1) * PD + gy + 1) * PD + (v + 1)) * 16 + cc;
                int ni = (gz * 64 + gy) * 64 + v;
                float2 yv = *(const float2*)&g_ypad[yi];
                float znl = __ldg(&nz[cc * SSS + ni]);
                float znh = __ldg(&nz[(cc + 1) * SSS + ni]);
                yv.x += (d[mt][nt][half * 2 + 0] + bl[nt]) * DT_F + SN_F * znl;
                yv.y += (d[mt][nt][half * 2 + 1] + bh[nt]) * DT_F + SN_F * znh;
                *(float2*)&g_ypad[yi] = yv;
                float2 yt;
                yt.x = __uint_as_float(cvt_tf32(yv.x));
                yt.y = __uint_as_float(cvt_tf32(yv.y));
                *(float2*)&g_ytf32[yi] = yt;
            }
        }
    }
}

// ---------------------------------------------------------------------------
// Launch: inputs = [x, integration_time, w1, b1, w2, b2, noise]
// ---------------------------------------------------------------------------
extern "C" void kernel_launch(void* const* d_in, const int* in_sizes, int n_in,
                              void* d_out, int out_size) {
    const float* x  = (const float*)d_in[0];
    const float* w1 = (const float*)d_in[2];
    const float* b1 = (const float*)d_in[3];
    const float* w2 = (const float*)d_in[4];
    const float* b2 = (const float*)d_in[5];
    const float* nz = (const float*)d_in[6];

    cudaFuncSetAttribute(conv1_k,
        cudaFuncAttributeMaxDynamicSharedMemorySize, 2 * T1CH);
    cudaFuncSetAttribute(conv2_k,
        cudaFuncAttributeMaxDynamicSharedMemorySize, 2 * T2CH);

    reorder_k<<<(27648 + 255) / 256, 256>>>(w1, w2);
    pack_k<<<NELEM / 256, 256>>>(x);

    dim3 cgrid1(32, 64);   // conv1: y:2 x z:1 tiles
    dim3 cgrid2(16, 32);   // conv2: y:4 x z:2 tiles
    for (int s = 0; s < NSTEPS; s++) {
        conv1_k<<<cgrid1, 256, 2 * T1CH>>>(b1);
        conv2_k<<<cgrid2, 256, 2 * T2CH>>>(b2, nz + (size_t)s * NELEM);
    }

    unpack_k<<<NELEM / 256, 256>>>((float*)d_out);
}